// round 7
// baseline (speedup 1.0000x reference)
#include <cuda_runtime.h>
#include <cstdint>
#include <math.h>

#define BB 8
#define CC 256
#define HH 96
#define WW 128
#define HWSZ (HH*WW)
#define RD 4
#define ND 9
#define TILE_H 8
#define TILE_W 16
#define NTHREADS 288          // 4 g * 8 ty * 9 dy
#define CHUNK 8
#define NCHUNK 32

// padded smem row strides (bank-conflict-free across ty)
#define FQ_PITCH 28           // >= 24 halo cols
#define FR_PITCH 20           // >= 16 cols
#define FQ_STG (CHUNK*16*FQ_PITCH)   // 3584 floats per buffer
#define FR_STG (CHUNK*8*FR_PITCH)    // 1280 floats per buffer
#define FQ_F (2*FQ_STG)
#define FR_F (2*FR_STG)
#define FRN_F 128             // 8*16
#define FQN_F 448             // 16*28 (padded)
#define SMEM_FLOATS (FQ_F + FR_F + FRN_F + FQN_F)
#define SMEM_BYTES  (SMEM_FLOATS * 4)

#define FQ_SLOTS 768          // 8ch * 16row * 6 c16
#define FR_SLOTS 256          // 8ch * 8row * 4 c16
#define TOT_SLOTS (FQ_SLOTS + FR_SLOTS)   // 1024

__device__ __forceinline__ void cpasync16(unsigned sa, const float* src) {
    asm volatile("cp.async.cg.shared.global [%0], [%1], 16;\n" :: "r"(sa), "l"(src));
}
__device__ __forceinline__ unsigned smem_u32(const void* p) {
    return (unsigned)__cvta_generic_to_shared(p);
}

#define STAGE(BUFBIT) do {                                                  \
    _Pragma("unroll")                                                       \
    for (int it = 0; it < 4; ++it) {                                        \
        if (val[it]) cpasync16(dst[it] + (BUFBIT) * dlt[it], src[it]);      \
        src[it] += (size_t)CHUNK * HWSZ;                                    \
    }                                                                       \
    asm volatile("cp.async.commit_group;\n");                               \
} while (0)

#define COMP(BUFBIT) do {                                                   \
    const float* sfqb_ = sm + (BUFBIT) * FQ_STG;                            \
    const float* sfrb_ = sm + FQ_F + (BUFBIT) * FR_STG;                     \
    _Pragma("unroll")                                                       \
    for (int ch = 0; ch < CHUNK; ++ch) {                                    \
        const float* fqc = sfqb_ + ch * (16*FQ_PITCH);                      \
        const float* frc = sfrb_ + ch * (8*FR_PITCH);                       \
        float4 f4 = *(const float4*)(frc + ty * FR_PITCH + 4 * g);          \
        const float* rp = fqc + (ty + dy) * FQ_PITCH + 4 * g;               \
        float4 q0 = *(const float4*)(rp);                                   \
        float4 q1 = *(const float4*)(rp + 4);                               \
        float4 q2 = *(const float4*)(rp + 8);                               \
        float qv = fqc[o0];                                                 \
        fqs0 = fmaf(qv, qv, fqs0);                                          \
        if (tid < 96) { float qv1 = fqc[o1];                                \
                        fqs1 = fmaf(qv1, qv1, fqs1); }                      \
        if (dy == RD) {                                                     \
            frs0 = fmaf(f4.x, f4.x, frs0); frs1 = fmaf(f4.y, f4.y, frs1);   \
            frs2 = fmaf(f4.z, f4.z, frs2); frs3 = fmaf(f4.w, f4.w, frs3);   \
        }                                                                   \
        float fv[4] = {f4.x, f4.y, f4.z, f4.w};                             \
        float q[12] = {q0.x,q0.y,q0.z,q0.w, q1.x,q1.y,q1.z,q1.w,            \
                       q2.x,q2.y,q2.z,q2.w};                                \
        _Pragma("unroll")                                                   \
        for (int i = 0; i < 4; ++i)                                         \
            _Pragma("unroll")                                               \
            for (int dx = 0; dx < ND; ++dx)                                 \
                acc[i*ND + dx] = fmaf(fv[i], q[i + dx], acc[i*ND + dx]);    \
    }                                                                       \
} while (0)

__global__ __launch_bounds__(NTHREADS, 2)
void corr_kernel(const float* __restrict__ fr, const float* __restrict__ fq,
                 float* __restrict__ out) {
    extern __shared__ float sm[];
    float* s_fq  = sm;
    float* s_fr  = sm + FQ_F;
    float* s_frn = sm + FQ_F + FR_F;
    float* s_fqn = s_frn + FRN_F;

    const int b  = blockIdx.z;
    const int h0 = blockIdx.y * TILE_H;
    const int w0 = blockIdx.x * TILE_W;
    const int tid = threadIdx.x;
    const int g  = tid & 3;
    const int ty = (tid >> 2) & 7;
    const int dy = tid >> 5;          // warp-uniform

    const float* frb = fr + (size_t)b * CC * HWSZ;
    const float* fqb = fq + (size_t)b * CC * HWSZ;

    // fq-norm positions (16x24 halo = 384; pos0 = tid, pos1 = tid+288 for tid<96)
    const int o0 = (tid / 24) * FQ_PITCH + (tid % 24);
    const int p1 = tid + NTHREADS;
    const int o1 = (p1 / 24) * FQ_PITCH + (p1 % 24);

    // ---- precompute staging slots ----
    const float* src[4];
    unsigned dst[4], dlt[4];
    bool val[4];
    #pragma unroll
    for (int it = 0; it < 4; ++it) {
        int idx = tid + it * NTHREADS;
        val[it] = false; src[it] = frb; dst[it] = smem_u32(sm); dlt[it] = 0;
        if (idx < FQ_SLOTS) {                    // fq halo slot
            int ch  = idx / 96;
            int rem = idx - ch * 96;
            int row = rem / 6;
            int c16 = rem - row * 6;
            int hg = h0 + row - RD;
            int wg = w0 + c16 * 4 - RD;
            bool v = (hg >= 0 && hg < HH && wg >= 0 && wg <= WW - 4);
            val[it] = v;
            dst[it] = smem_u32(s_fq + (ch * 16 + row) * FQ_PITCH + c16 * 4);
            dlt[it] = FQ_STG * 4;
            if (v) src[it] = fqb + (size_t)ch * HWSZ + hg * WW + wg;
        } else if (idx < TOT_SLOTS) {            // fr slot
            int j   = idx - FQ_SLOTS;
            int ch  = j >> 5;
            int rem = j & 31;
            int row = rem >> 2;
            int c16 = rem & 3;
            val[it] = true;
            dst[it] = smem_u32(s_fr + (ch * 8 + row) * FR_PITCH + c16 * 4);
            dlt[it] = FR_STG * 4;
            src[it] = frb + (size_t)ch * HWSZ + (h0 + row) * WW + (w0 + c16 * 4);
        }
    }

    // zero fq buffers once (OOB halo slots never overwritten by cp.async)
    for (int i = tid; i < FQ_F; i += NTHREADS) s_fq[i] = 0.f;
    __syncthreads();   // order zero-stores before any cp.async into same buffer

    float acc[36];
    #pragma unroll
    for (int i = 0; i < 36; ++i) acc[i] = 0.f;
    float frs0 = 0.f, frs1 = 0.f, frs2 = 0.f, frs3 = 0.f;
    float fqs0 = 0.f, fqs1 = 0.f;

    STAGE(0);   // chunk 0 -> buf0

    #pragma unroll 1
    for (int kk = 0; kk < NCHUNK / 2; ++kk) {
        STAGE(1);                                     // chunk 2kk+1 -> buf1
        asm volatile("cp.async.wait_group 1;\n");
        __syncthreads();
        COMP(0);
        __syncthreads();
        if (kk < NCHUNK / 2 - 1) {
            STAGE(0);                                 // chunk 2kk+2 -> buf0
            asm volatile("cp.async.wait_group 1;\n");
        } else {
            asm volatile("cp.async.wait_group 0;\n");
        }
        __syncthreads();
        COMP(1);
        __syncthreads();
    }

    // ---- exchange inverse norms ----
    if (dy == RD) {
        float s[4] = {frs0, frs1, frs2, frs3};
        #pragma unroll
        for (int i = 0; i < 4; ++i)
            s_frn[ty * TILE_W + 4 * g + i] = 1.0f / fmaxf(sqrtf(s[i]), 1e-12f);
    }
    s_fqn[o0] = 1.0f / fmaxf(sqrtf(fqs0), 1e-12f);
    if (tid < 96)
        s_fqn[o1] = 1.0f / fmaxf(sqrtf(fqs1), 1e-12f);
    __syncthreads();

    const int h = h0 + ty;
    const int w_base = w0 + 4 * g;

    float invfr[4];
    #pragma unroll
    for (int i = 0; i < 4; ++i)
        invfr[i] = s_frn[ty * TILE_W + 4 * g + i];

    float invq[12];
    #pragma unroll
    for (int j = 0; j < 12; ++j)
        invq[j] = s_fqn[(ty + dy) * FQ_PITCH + 4 * g + j];

    const float scale = 1.0f / (float)CC;
    #pragma unroll
    for (int dx = 0; dx < ND; ++dx) {
        float4 o;
        o.x = acc[0*ND + dx] * invfr[0] * invq[0 + dx] * scale;
        o.y = acc[1*ND + dx] * invfr[1] * invq[1 + dx] * scale;
        o.z = acc[2*ND + dx] * invfr[2] * invq[2 + dx] * scale;
        o.w = acc[3*ND + dx] * invfr[3] * invq[3 + dx] * scale;
        size_t off = (((size_t)b * (ND*ND) + (size_t)(dy*ND + dx)) * HH + h) * WW + w_base;
        *(float4*)&out[off] = o;
    }
}

extern "C" void kernel_launch(void* const* d_in, const int* in_sizes, int n_in,
                              void* d_out, int out_size) {
    const float* fr = (const float*)d_in[0];
    const float* fq = (const float*)d_in[1];
    float* out = (float*)d_out;
    (void)in_sizes; (void)n_in; (void)out_size;

    cudaFuncSetAttribute(corr_kernel, cudaFuncAttributeMaxDynamicSharedMemorySize, SMEM_BYTES);

    dim3 grid(WW / TILE_W, HH / TILE_H, BB);   // (8, 12, 8) = 768 CTAs
    corr_kernel<<<grid, NTHREADS, SMEM_BYTES>>>(fr, fq, out);
}

// round 8
// speedup vs baseline: 1.7158x; 1.7158x over previous
#include <cuda_runtime.h>
#include <cstdint>
#include <math.h>

#define BB 8
#define CC 256
#define HH 96
#define WW 128
#define HWSZ (HH*WW)
#define RD 4
#define ND 9
#define TILE_H 8
#define TILE_W 32
#define NTHREADS 576
#define CHUNK 8
#define NCHUNK 32
#define NBUF 4

#define FQ_STG 5120         // floats per fq buffer (8 ch * 16 * 40)
#define FR_STG 2048         // floats per fr buffer (8 ch * 8 * 32)
#define FQ_F (NBUF*FQ_STG)
#define FR_F (NBUF*FR_STG)
#define SMEM_FLOATS (FQ_F + FR_F + 256 + 640)
#define SMEM_BYTES  (SMEM_FLOATS * 4)

__device__ __forceinline__ void cpasync16(unsigned sa, const float* src) {
    asm volatile("cp.async.cg.shared.global [%0], [%1], 16;\n" :: "r"(sa), "l"(src));
}
__device__ __forceinline__ unsigned smem_u32(const void* p) {
    return (unsigned)__cvta_generic_to_shared(p);
}

// stage chunk into ring buffer BUFL (literal 0..3); always commits a group
#define STAGE(BUFL) do {                                                    \
    _Pragma("unroll")                                                       \
    for (int it = 0; it < 4; ++it) {                                        \
        if (val[it]) cpasync16(dst[it] + (BUFL) * dlt[it], src[it]);        \
        src[it] += (size_t)CHUNK * HWSZ;                                    \
    }                                                                       \
    asm volatile("cp.async.commit_group;\n");                               \
} while (0)

#define COMP(BUFL) do {                                                     \
    const float* sfqb_ = sm + (BUFL) * FQ_STG;                              \
    const float* sfrb_ = sm + FQ_F + (BUFL) * FR_STG;                       \
    _Pragma("unroll")                                                       \
    for (int ch = 0; ch < CHUNK; ++ch) {                                    \
        const float* fqc = sfqb_ + ch * 640;                                \
        const float* frc = sfrb_ + ch * 256;                                \
        float4 f4 = *(const float4*)(frc + ty * 32 + 4 * g);                \
        const float* rp = fqc + (ty + dy) * 40 + 4 * g;                     \
        float4 q0 = *(const float4*)(rp);                                   \
        float4 q1 = *(const float4*)(rp + 4);                               \
        float4 q2 = *(const float4*)(rp + 8);                               \
        float qv = fqc[tid];                                                \
        fqs0 = fmaf(qv, qv, fqs0);                                          \
        if (tid < 64) { float qv1 = fqc[tid + NTHREADS];                    \
                        fqs1 = fmaf(qv1, qv1, fqs1); }                      \
        if (dy == RD) {                                                     \
            frs0 = fmaf(f4.x, f4.x, frs0); frs1 = fmaf(f4.y, f4.y, frs1);   \
            frs2 = fmaf(f4.z, f4.z, frs2); frs3 = fmaf(f4.w, f4.w, frs3);   \
        }                                                                   \
        float fv[4] = {f4.x, f4.y, f4.z, f4.w};                             \
        float q[12] = {q0.x,q0.y,q0.z,q0.w, q1.x,q1.y,q1.z,q1.w,            \
                       q2.x,q2.y,q2.z,q2.w};                                \
        _Pragma("unroll")                                                   \
        for (int i = 0; i < 4; ++i)                                         \
            _Pragma("unroll")                                               \
            for (int dx = 0; dx < ND; ++dx)                                 \
                acc[i*ND + dx] = fmaf(fv[i], q[i + dx], acc[i*ND + dx]);    \
    }                                                                       \
} while (0)

// one pipeline iteration: stage chunk K+2 (ring slot literal SB), wait chunk K,
// single barrier, compute chunk K (ring slot literal CB)
#define ITER(K, SB, CB) do {                                                \
    if ((K) + 2 < NCHUNK) { STAGE(SB); }                                    \
    else { asm volatile("cp.async.commit_group;\n"); }                      \
    asm volatile("cp.async.wait_group 2;\n");                               \
    __syncthreads();                                                        \
    COMP(CB);                                                               \
} while (0)

__global__ __launch_bounds__(NTHREADS, 1)
void corr_kernel(const float* __restrict__ fr, const float* __restrict__ fq,
                 float* __restrict__ out) {
    extern __shared__ float sm[];
    float* s_fq  = sm;
    float* s_fr  = sm + FQ_F;
    float* s_frn = sm + FQ_F + FR_F;
    float* s_fqn = s_frn + 256;

    const int b  = blockIdx.z;
    const int h0 = blockIdx.y * TILE_H;
    const int w0 = blockIdx.x * TILE_W;
    const int tid = threadIdx.x;
    const int g  = tid & 7;
    const int ty = (tid >> 3) & 7;
    const int dy = tid >> 6;

    const float* frb = fr + (size_t)b * CC * HWSZ;
    const float* fqb = fq + (size_t)b * CC * HWSZ;

    // ---- precompute staging slots (fixed per thread across all chunks) ----
    const float* src[4];
    unsigned dst[4], dlt[4];
    bool val[4];
    #pragma unroll
    for (int it = 0; it < 4; ++it) {
        int idx = tid + it * NTHREADS;
        val[it] = false; src[it] = frb; dst[it] = smem_u32(sm); dlt[it] = 0;
        if (idx < 1280) {                       // fq halo tile slot
            int ch  = idx / 160;
            int rem = idx - ch * 160;
            int row = rem / 10;
            int c16 = rem - row * 10;
            int hg = h0 + row - RD;
            int wg = w0 + c16 * 4 - RD;
            bool v = (hg >= 0 && hg < HH && wg >= 0 && wg <= WW - 4);
            val[it] = v;
            dst[it] = smem_u32(s_fq + (ch * 16 + row) * 40 + c16 * 4);
            dlt[it] = FQ_STG * 4;
            if (v) src[it] = fqb + (size_t)ch * HWSZ + hg * WW + wg;
        } else if (idx < 1792) {                // fr tile slot
            int j   = idx - 1280;
            int ch  = j >> 6;
            int rem = j & 63;
            int row = rem >> 3;
            int c16 = rem & 7;
            val[it] = true;
            dst[it] = smem_u32(s_fr + (ch * 8 + row) * 32 + c16 * 4);
            dlt[it] = FR_STG * 4;
            src[it] = frb + (size_t)ch * HWSZ + (h0 + row) * WW + (w0 + c16 * 4);
        }
    }

    // zero fq buffers once (OOB halo slots never overwritten by cp.async)
    for (int i = tid; i < FQ_F; i += NTHREADS) s_fq[i] = 0.f;
    __syncthreads();   // order zero-stores before any cp.async into same buffers

    float acc[36];
    #pragma unroll
    for (int i = 0; i < 36; ++i) acc[i] = 0.f;
    float frs0 = 0.f, frs1 = 0.f, frs2 = 0.f, frs3 = 0.f;
    float fqs0 = 0.f, fqs1 = 0.f;

    STAGE(0);   // chunk 0 -> buf0
    STAGE(1);   // chunk 1 -> buf1

    #pragma unroll 1
    for (int kb = 0; kb < NCHUNK / 4; ++kb) {
        const int k0 = kb * 4;
        ITER(k0 + 0, 2, 0);
        ITER(k0 + 1, 3, 1);
        ITER(k0 + 2, 0, 2);
        ITER(k0 + 3, 1, 3);
    }

    // ---- exchange inverse norms through smem ----
    if (dy == RD) {
        float s[4] = {frs0, frs1, frs2, frs3};
        #pragma unroll
        for (int i = 0; i < 4; ++i)
            s_frn[ty * 32 + 4 * g + i] = 1.0f / fmaxf(sqrtf(s[i]), 1e-12f);
    }
    s_fqn[tid] = 1.0f / fmaxf(sqrtf(fqs0), 1e-12f);
    if (tid < 64)
        s_fqn[tid + NTHREADS] = 1.0f / fmaxf(sqrtf(fqs1), 1e-12f);
    __syncthreads();

    const int h = h0 + ty;
    const int w_base = w0 + 4 * g;

    float invfr[4];
    #pragma unroll
    for (int i = 0; i < 4; ++i)
        invfr[i] = s_frn[ty * 32 + 4 * g + i];

    float invq[12];
    #pragma unroll
    for (int j = 0; j < 12; ++j)
        invq[j] = s_fqn[(ty + dy) * 40 + 4 * g + j];

    const float scale = 1.0f / (float)CC;
    #pragma unroll
    for (int dx = 0; dx < ND; ++dx) {
        float4 o;
        o.x = acc[0*ND + dx] * invfr[0] * invq[0 + dx] * scale;
        o.y = acc[1*ND + dx] * invfr[1] * invq[1 + dx] * scale;
        o.z = acc[2*ND + dx] * invfr[2] * invq[2 + dx] * scale;
        o.w = acc[3*ND + dx] * invfr[3] * invq[3 + dx] * scale;
        size_t off = (((size_t)b * (ND*ND) + (size_t)(dy*ND + dx)) * HH + h) * WW + w_base;
        *(float4*)&out[off] = o;
    }
}

extern "C" void kernel_launch(void* const* d_in, const int* in_sizes, int n_in,
                              void* d_out, int out_size) {
    const float* fr = (const float*)d_in[0];
    const float* fq = (const float*)d_in[1];
    float* out = (float*)d_out;
    (void)in_sizes; (void)n_in; (void)out_size;

    cudaFuncSetAttribute(corr_kernel, cudaFuncAttributeMaxDynamicSharedMemorySize, SMEM_BYTES);

    dim3 grid(WW / TILE_W, HH / TILE_H, BB);   // (4, 12, 8) = 384 CTAs
    corr_kernel<<<grid, NTHREADS, SMEM_BYTES>>>(fr, fq, out);
}

// round 9
// speedup vs baseline: 1.7348x; 1.0111x over previous
#include <cuda_runtime.h>
#include <cstdint>
#include <math.h>

#define BB 8
#define CC 256
#define HH 96
#define WW 128
#define HWSZ (HH*WW)
#define RD 4
#define ND 9
#define TILE_H 8
#define TILE_W 32
#define NTHREADS 288          // 4 g(8px) * 8 ty * 9 dy
#define CHUNK 8
#define NCHUNK 32
#define NBUF 4

#define FQ_PITCH 44           // floats per fq halo row (40 used), conflict-free
#define FR_PITCH 36           // floats per fr row (32 used), conflict-free
#define FQ_STG (CHUNK*16*FQ_PITCH)   // 5632 floats per buffer
#define FR_STG (CHUNK*8*FR_PITCH)    // 2304 floats per buffer
#define FQ_F (NBUF*FQ_STG)           // 22528
#define FR_F (NBUF*FR_STG)           // 9216
#define FRN_F 256             // 8*32
#define FQN_F 704             // 16*44
#define SMEM_FLOATS (FQ_F + FR_F + FRN_F + FQN_F)
#define SMEM_BYTES  (SMEM_FLOATS * 4)   // ~131KB

#define FQ_SLOTS 1280         // 8ch*16row*10c16
#define TOT_SLOTS 1792        // + 8ch*8row*8c16
#define NSLOT_IT 7            // ceil(1792/288)

__device__ __forceinline__ void cpasync16(unsigned sa, const float* src) {
    asm volatile("cp.async.cg.shared.global [%0], [%1], 16;\n" :: "r"(sa), "l"(src));
}
__device__ __forceinline__ unsigned smem_u32(const void* p) {
    return (unsigned)__cvta_generic_to_shared(p);
}

#define STAGE(BUFL) do {                                                    \
    _Pragma("unroll")                                                       \
    for (int it = 0; it < NSLOT_IT; ++it) {                                 \
        if (val[it]) cpasync16(dst[it] + (BUFL) * dlt[it], src[it]);        \
        src[it] += (size_t)CHUNK * HWSZ;                                    \
    }                                                                       \
    asm volatile("cp.async.commit_group;\n");                               \
} while (0)

#define COMP(BUFL) do {                                                     \
    const float* sfqb_ = sm + (BUFL) * FQ_STG;                              \
    const float* sfrb_ = sm + FQ_F + (BUFL) * FR_STG;                       \
    _Pragma("unroll")                                                       \
    for (int ch = 0; ch < CHUNK; ++ch) {                                    \
        const float* fqc = sfqb_ + ch * (16*FQ_PITCH);                      \
        const float* frc = sfrb_ + ch * (8*FR_PITCH);                       \
        float4 fA = *(const float4*)(frc + ty * FR_PITCH + 8 * g);          \
        float4 fB = *(const float4*)(frc + ty * FR_PITCH + 8 * g + 4);      \
        const float* rp = fqc + (ty + dy) * FQ_PITCH + 8 * g;               \
        float4 q0 = *(const float4*)(rp);                                   \
        float4 q1 = *(const float4*)(rp + 4);                               \
        float4 q2 = *(const float4*)(rp + 8);                               \
        float4 q3 = *(const float4*)(rp + 12);                              \
        float qv0 = fqc[o0], qv1 = fqc[o1];                                 \
        fqs0 = fmaf(qv0, qv0, fqs0);                                        \
        fqs1 = fmaf(qv1, qv1, fqs1);                                        \
        if (tid < 64) { float qv2 = fqc[o2];                                \
                        fqs2 = fmaf(qv2, qv2, fqs2); }                      \
        float fv[8] = {fA.x, fA.y, fA.z, fA.w, fB.x, fB.y, fB.z, fB.w};     \
        if (dy == RD) {                                                     \
            _Pragma("unroll")                                               \
            for (int i = 0; i < 8; ++i) frs[i] = fmaf(fv[i], fv[i], frs[i]);\
        }                                                                   \
        float q[16] = {q0.x,q0.y,q0.z,q0.w, q1.x,q1.y,q1.z,q1.w,            \
                       q2.x,q2.y,q2.z,q2.w, q3.x,q3.y,q3.z,q3.w};           \
        _Pragma("unroll")                                                   \
        for (int i = 0; i < 8; ++i)                                         \
            _Pragma("unroll")                                               \
            for (int dx = 0; dx < ND; ++dx)                                 \
                acc[i*ND + dx] = fmaf(fv[i], q[i + dx], acc[i*ND + dx]);    \
    }                                                                       \
} while (0)

#define ITER(K, SB, CB) do {                                                \
    if ((K) + 2 < NCHUNK) { STAGE(SB); }                                    \
    else { asm volatile("cp.async.commit_group;\n"); }                      \
    asm volatile("cp.async.wait_group 2;\n");                               \
    __syncthreads();                                                        \
    COMP(CB);                                                               \
} while (0)

__global__ __launch_bounds__(NTHREADS, 1)
void corr_kernel(const float* __restrict__ fr, const float* __restrict__ fq,
                 float* __restrict__ out) {
    extern __shared__ float sm[];
    float* s_fq  = sm;
    float* s_fr  = sm + FQ_F;
    float* s_frn = sm + FQ_F + FR_F;
    float* s_fqn = s_frn + FRN_F;

    const int b  = blockIdx.z;
    const int h0 = blockIdx.y * TILE_H;
    const int w0 = blockIdx.x * TILE_W;
    const int tid = threadIdx.x;
    const int g  = tid & 3;           // 8-px group
    const int ty = (tid >> 2) & 7;
    const int dy = tid >> 5;          // warp-uniform, 0..8

    const float* frb = fr + (size_t)b * CC * HWSZ;
    const float* fqb = fq + (size_t)b * CC * HWSZ;

    // fq-norm halo positions (16x40 = 640): tid, tid+288, tid+576(tid<64)
    const int o0 = (tid / 40) * FQ_PITCH + (tid % 40);
    const int p1 = tid + NTHREADS;
    const int o1 = (p1 / 40) * FQ_PITCH + (p1 % 40);
    const int p2 = tid + 2 * NTHREADS;
    const int o2 = (p2 / 40) * FQ_PITCH + (p2 % 40);

    // ---- precompute staging slots ----
    const float* src[NSLOT_IT];
    unsigned dst[NSLOT_IT], dlt[NSLOT_IT];
    bool val[NSLOT_IT];
    #pragma unroll
    for (int it = 0; it < NSLOT_IT; ++it) {
        int idx = tid + it * NTHREADS;
        val[it] = false; src[it] = frb; dst[it] = smem_u32(sm); dlt[it] = 0;
        if (idx < FQ_SLOTS) {                    // fq halo slot
            int ch  = idx / 160;
            int rem = idx - ch * 160;
            int row = rem / 10;
            int c16 = rem - row * 10;
            int hg = h0 + row - RD;
            int wg = w0 + c16 * 4 - RD;
            bool v = (hg >= 0 && hg < HH && wg >= 0 && wg <= WW - 4);
            val[it] = v;
            dst[it] = smem_u32(s_fq + (ch * 16 + row) * FQ_PITCH + c16 * 4);
            dlt[it] = FQ_STG * 4;
            if (v) src[it] = fqb + (size_t)ch * HWSZ + hg * WW + wg;
        } else if (idx < TOT_SLOTS) {            // fr slot
            int j   = idx - FQ_SLOTS;
            int ch  = j >> 6;
            int rem = j & 63;
            int row = rem >> 3;
            int c16 = rem & 7;
            val[it] = true;
            dst[it] = smem_u32(s_fr + (ch * 8 + row) * FR_PITCH + c16 * 4);
            dlt[it] = FR_STG * 4;
            src[it] = frb + (size_t)ch * HWSZ + (h0 + row) * WW + (w0 + c16 * 4);
        }
    }

    // zero fq buffers once (OOB halo + pad cols never overwritten by cp.async)
    for (int i = tid; i < FQ_F; i += NTHREADS) s_fq[i] = 0.f;
    __syncthreads();   // order zero-stores before any cp.async into same buffers

    float acc[72];
    #pragma unroll
    for (int i = 0; i < 72; ++i) acc[i] = 0.f;
    float frs[8] = {0,0,0,0,0,0,0,0};
    float fqs0 = 0.f, fqs1 = 0.f, fqs2 = 0.f;

    STAGE(0);   // chunk 0 -> buf0
    STAGE(1);   // chunk 1 -> buf1

    #pragma unroll 1
    for (int kb = 0; kb < NCHUNK / 4; ++kb) {
        const int k0 = kb * 4;
        ITER(k0 + 0, 2, 0);
        ITER(k0 + 1, 3, 1);
        ITER(k0 + 2, 0, 2);
        ITER(k0 + 3, 1, 3);
    }

    // ---- exchange inverse norms through smem ----
    if (dy == RD) {
        #pragma unroll
        for (int i = 0; i < 8; ++i)
            s_frn[ty * TILE_W + 8 * g + i] = 1.0f / fmaxf(sqrtf(frs[i]), 1e-12f);
    }
    s_fqn[o0] = 1.0f / fmaxf(sqrtf(fqs0), 1e-12f);
    s_fqn[o1] = 1.0f / fmaxf(sqrtf(fqs1), 1e-12f);
    if (tid < 64)
        s_fqn[o2] = 1.0f / fmaxf(sqrtf(fqs2), 1e-12f);
    __syncthreads();

    const int h = h0 + ty;
    const int w_base = w0 + 8 * g;

    float invfr[8];
    #pragma unroll
    for (int i = 0; i < 8; ++i)
        invfr[i] = s_frn[ty * TILE_W + 8 * g + i];

    float invq[16];
    #pragma unroll
    for (int j = 0; j < 16; ++j)
        invq[j] = s_fqn[(ty + dy) * FQ_PITCH + 8 * g + j];

    const float scale = 1.0f / (float)CC;
    #pragma unroll
    for (int dx = 0; dx < ND; ++dx) {
        float4 oA, oB;
        oA.x = acc[0*ND + dx] * invfr[0] * invq[0 + dx] * scale;
        oA.y = acc[1*ND + dx] * invfr[1] * invq[1 + dx] * scale;
        oA.z = acc[2*ND + dx] * invfr[2] * invq[2 + dx] * scale;
        oA.w = acc[3*ND + dx] * invfr[3] * invq[3 + dx] * scale;
        oB.x = acc[4*ND + dx] * invfr[4] * invq[4 + dx] * scale;
        oB.y = acc[5*ND + dx] * invfr[5] * invq[5 + dx] * scale;
        oB.z = acc[6*ND + dx] * invfr[6] * invq[6 + dx] * scale;
        oB.w = acc[7*ND + dx] * invfr[7] * invq[7 + dx] * scale;
        size_t off = (((size_t)b * (ND*ND) + (size_t)(dy*ND + dx)) * HH + h) * WW + w_base;
        *(float4*)&out[off]     = oA;
        *(float4*)&out[off + 4] = oB;
    }
}

extern "C" void kernel_launch(void* const* d_in, const int* in_sizes, int n_in,
                              void* d_out, int out_size) {
    const float* fr = (const float*)d_in[0];
    const float* fq = (const float*)d_in[1];
    float* out = (float*)d_out;
    (void)in_sizes; (void)n_in; (void)out_size;

    cudaFuncSetAttribute(corr_kernel, cudaFuncAttributeMaxDynamicSharedMemorySize, SMEM_BYTES);

    dim3 grid(WW / TILE_W, HH / TILE_H, BB);   // (4, 12, 8) = 384 CTAs
    corr_kernel<<<grid, NTHREADS, SMEM_BYTES>>>(fr, fq, out);
}